// round 6
// baseline (speedup 1.0000x reference)
#include <cuda_runtime.h>

// CrossCCC: out = 1 - mean_n CCC(lag n), n = 0..249
// Single fused kernel, one smem tile per block (perfect load balance,
// ~4 CTAs/SM for latency hiding). Last block (atomic ticket) reduces all
// per-block partials and computes the final scalar. Deterministic: the
// finalize reads every block's partials in a fixed order.

#define NL        256      // padded lag count (250 used)
#define NLAGS     250
#define CHUNK     1696     // multiple of 32; ~590 chunks for T=1e6 (~4/SM)
#define MAXBLK    1184     // grid cap (8 CTAs/SM reg limit)
#define NTHREADS  256

__device__ float d_Cpart[MAXBLK][NL];
__device__ float d_sums[MAXBLK][4];   // Sp, Qp, Sg, Qg partials
__device__ unsigned int d_ticket;      // zero-init; last block resets to 0

__global__ void __launch_bounds__(NTHREADS)
fused_kernel(const float* __restrict__ p, const float* __restrict__ g,
             float* __restrict__ out, int T, int nchunks) {
    __shared__ float sp[CHUNK];
    __shared__ float sg[CHUNK + NL];
    __shared__ float red[NTHREADS / 32];
    __shared__ int   s_last;

    const int tid  = threadIdx.x;
    const int n0   = (tid >> 3) * 8;   // 8 lags per thread
    const int jsub = tid & 7;          // 8 j-subthreads per lag group

    float acc[8];
#pragma unroll
    for (int i = 0; i < 8; i++) acc[i] = 0.f;
    float s_p = 0.f, q_p = 0.f, s_g = 0.f, q_g = 0.f;

    // grid-stride for generality; for T=1e6 each block runs exactly once
    for (int c = blockIdx.x; c < nchunks; c += gridDim.x) {
        const long long j0 = (long long)c * CHUNK;
        for (int i = tid; i < CHUNK; i += NTHREADS) {
            long long gi = j0 + i;
            float v = (gi < T) ? p[gi] : 0.f;
            sp[i] = v;
            s_p += v; q_p += v * v;
        }
        for (int i = tid; i < CHUNK + NL; i += NTHREADS) {
            long long gi = j0 + i;
            float v = (gi < T) ? g[gi] : 0.f;
            sg[i] = v;
            if (i < CHUNK) { s_g += v; q_g += v * v; }
        }
        __syncthreads();

        // 8 lags x 4 j register blocking: 4x LDS.128 per 32 FMAs
        const float* gbase = sg + n0;
#pragma unroll 2
        for (int k = jsub * 4; k < CHUNK; k += 32) {
            float4 pv = *reinterpret_cast<const float4*>(sp + k);
            const float* gw = gbase + k;
            float4 g0 = *reinterpret_cast<const float4*>(gw);
            float4 g1 = *reinterpret_cast<const float4*>(gw + 4);
            float4 g2 = *reinterpret_cast<const float4*>(gw + 8);
            float gv[12] = {g0.x, g0.y, g0.z, g0.w,
                            g1.x, g1.y, g1.z, g1.w,
                            g2.x, g2.y, g2.z, g2.w};
            float pj[4] = {pv.x, pv.y, pv.z, pv.w};
#pragma unroll
            for (int dj = 0; dj < 4; dj++)
#pragma unroll
                for (int dn = 0; dn < 8; dn++)
                    acc[dn] = fmaf(pj[dj], gv[dj + dn], acc[dn]);
        }
        __syncthreads();
    }

    // reduce 8-lane j-subgroups (contiguous lanes) via shuffle
#pragma unroll
    for (int dn = 0; dn < 8; dn++) {
        float v = acc[dn];
        v += __shfl_down_sync(0xFFFFFFFFu, v, 4);
        v += __shfl_down_sync(0xFFFFFFFFu, v, 2);
        v += __shfl_down_sync(0xFFFFFFFFu, v, 1);
        acc[dn] = v;
    }
    if (jsub == 0) {
#pragma unroll
        for (int dn = 0; dn < 8; dn++)
            d_Cpart[blockIdx.x][n0 + dn] = acc[dn];
    }

    // block-reduce the 4 scalar sums
    float vals[4] = {s_p, q_p, s_g, q_g};
    for (int v = 0; v < 4; v++) {
        float x = vals[v];
#pragma unroll
        for (int off = 16; off > 0; off >>= 1)
            x += __shfl_down_sync(0xFFFFFFFFu, x, off);
        if ((tid & 31) == 0) red[tid >> 5] = x;
        __syncthreads();
        if (tid == 0) {
            float s = 0.f;
            for (int w = 0; w < NTHREADS / 32; w++) s += red[w];
            d_sums[blockIdx.x][v] = s;
        }
        __syncthreads();
    }

    // ---- last-block election ----
    __threadfence();   // make this block's partials globally visible
    if (tid == 0) {
        unsigned int old = atomicAdd(&d_ticket, 1u);
        s_last = (old == gridDim.x - 1) ? 1 : 0;
    }
    __syncthreads();
    if (!s_last) return;

    // =====================================================================
    // Finalize (runs in the last block; partials are L2-hot)
    // =====================================================================
    const int nblk = gridDim.x;
    __shared__ double sh_sums[4];
    __shared__ double prefp[NL];
    __shared__ double prefq[NL];
    __shared__ double cccsh[NL];

    // ---- cross-block C reduction: one lag per thread, 4 accumulators ----
    double Cn;
    {
        const int lag = tid;
        float a0 = 0.f, a1 = 0.f, a2 = 0.f, a3 = 0.f;
        int b = 0;
        for (; b + 3 < nblk; b += 4) {
            a0 += d_Cpart[b    ][lag];
            a1 += d_Cpart[b + 1][lag];
            a2 += d_Cpart[b + 2][lag];
            a3 += d_Cpart[b + 3][lag];
        }
        for (; b < nblk; b++) a0 += d_Cpart[b][lag];
        Cn = (double)((a0 + a1) + (a2 + a3));
    }

    // ---- scalar sums (4 warps, one value each) ----
    if (tid < 128) {
        int v = tid >> 5, lane = tid & 31;
        double sv = 0.0;
        for (int b = lane; b < nblk; b += 32) sv += (double)d_sums[b][v];
#pragma unroll
        for (int off = 16; off > 0; off >>= 1)
            sv += __shfl_down_sync(0xFFFFFFFFu, sv, off);
        if (lane == 0) sh_sums[v] = sv;
    }

    // ---- tail prefix sums: tail_p(n) = sum_{i=1..n} p[T-i] ----
    {
        double w = (tid >= 1) ? (double)p[T - tid] : 0.0;
        prefp[tid] = w;
        prefq[tid] = w * w;
    }
    __syncthreads();
#pragma unroll
    for (int off = 1; off < NL; off <<= 1) {
        double a = 0.0, b = 0.0;
        if (tid >= off) { a = prefp[tid - off]; b = prefq[tid - off]; }
        __syncthreads();
        prefp[tid] += a; prefq[tid] += b;
        __syncthreads();
    }

    // ---- per-lag CCC ----
    double ccc = 0.0;
    if (tid < NLAGS) {
        double tp = prefp[tid], tq = prefq[tid];   // pref[0] == 0
        const double Td  = (double)T;
        const double rT  = 1.0 / Td;
        const double rT1 = 1.0 / (Td - 1.0);
        double Sp = sh_sums[0] - tp, Qp = sh_sums[1] - tq;
        double Sg = sh_sums[2],      Qg = sh_sums[3];
        double mean_gt   = Sg * rT;
        double var_gt    = (Qg - Sg * Sg * rT) * rT1;
        double mean_pred = Sp * rT;
        double var_pred  = (Qp - Sp * Sp * rT) * rT1;
        double cov       = (Cn - mean_gt * Sp) * rT;
        double dm        = mean_gt - mean_pred;
        double denom     = var_gt + var_pred + dm * dm;
        ccc = 2.0 * cov / denom;
    }
    cccsh[tid] = ccc;   // lags 250..255 contribute 0
    __syncthreads();

#pragma unroll
    for (int off = NL / 2; off > 0; off >>= 1) {
        if (tid < off) cccsh[tid] += cccsh[tid + off];
        __syncthreads();
    }
    if (tid == 0) {
        out[0] = (float)(1.0 - cccsh[0] / (double)NLAGS);
        d_ticket = 0;   // restore for next graph replay
    }
}

extern "C" void kernel_launch(void* const* d_in, const int* in_sizes, int n_in,
                              void* d_out, int out_size) {
    const float* p = (const float*)d_in[0];   // prediction
    const float* g = (const float*)d_in[1];   // ground_truth
    int T = in_sizes[0];
    int nchunks = (T + CHUNK - 1) / CHUNK;
    int grid = nchunks < MAXBLK ? nchunks : MAXBLK;
    fused_kernel<<<grid, NTHREADS>>>(p, g, (float*)d_out, T, nchunks);
}

// round 7
// speedup vs baseline: 1.0468x; 1.0468x over previous
#include <cuda_runtime.h>

// CrossCCC: out = 1 - mean_n CCC(lag n), n = 0..249
// Single fused kernel; one smem tile per block; 16 lags x 4 j register
// blocking (64 FFMA per 6 LDS.128); last block finalizes via atomic ticket.

#define NL        256      // padded lag count (250 used)
#define NLAGS     250
#define CHUNK     2048     // multiple of 64
#define MAXBLK    512
#define NTHREADS  256

__device__ float d_Cpart[MAXBLK][NL];
__device__ float d_sums[MAXBLK][4];   // Sp, Qp, Sg, Qg partials
__device__ unsigned int d_ticket;     // zero-init; last block resets to 0

__global__ void __launch_bounds__(NTHREADS, 4)
fused_kernel(const float* __restrict__ p, const float* __restrict__ g,
             float* __restrict__ out, int T, int nchunks) {
    __shared__ float sp[CHUNK];
    __shared__ float sg[CHUNK + NL];
    __shared__ float red[NTHREADS / 32];
    __shared__ int   s_last;

    const int tid  = threadIdx.x;
    const int n0   = (tid >> 4) * 16;   // 16 lags per thread
    const int jsub = tid & 15;          // 16 j-subthreads per lag group

    float acc[16];
#pragma unroll
    for (int i = 0; i < 16; i++) acc[i] = 0.f;
    float s_p = 0.f, q_p = 0.f, s_g = 0.f, q_g = 0.f;

    for (int c = blockIdx.x; c < nchunks; c += gridDim.x) {
        const long long j0 = (long long)c * CHUNK;

        if (j0 + CHUNK + NL <= (long long)T) {
            // fast path: vectorized loads, no bounds checks
            const float4* p4 = reinterpret_cast<const float4*>(p + j0);
            const float4* g4 = reinterpret_cast<const float4*>(g + j0);
            for (int i = tid; i < CHUNK / 4; i += NTHREADS) {
                float4 v = p4[i];
                *reinterpret_cast<float4*>(sp + 4 * i) = v;
                s_p += (v.x + v.y) + (v.z + v.w);
                q_p += (v.x * v.x + v.y * v.y) + (v.z * v.z + v.w * v.w);
            }
            for (int i = tid; i < (CHUNK + NL) / 4; i += NTHREADS) {
                float4 v = g4[i];
                *reinterpret_cast<float4*>(sg + 4 * i) = v;
                if (i < CHUNK / 4) {
                    s_g += (v.x + v.y) + (v.z + v.w);
                    q_g += (v.x * v.x + v.y * v.y) + (v.z * v.z + v.w * v.w);
                }
            }
        } else {
            // edge path: scalar with zero padding
            for (int i = tid; i < CHUNK; i += NTHREADS) {
                long long gi = j0 + i;
                float v = (gi < T) ? p[gi] : 0.f;
                sp[i] = v;
                s_p += v; q_p += v * v;
            }
            for (int i = tid; i < CHUNK + NL; i += NTHREADS) {
                long long gi = j0 + i;
                float v = (gi < T) ? g[gi] : 0.f;
                sg[i] = v;
                if (i < CHUNK) { s_g += v; q_g += v * v; }
            }
        }
        __syncthreads();

        // 16 lags x 4 j register blocking: 6x LDS.128 per 64 FMAs
        const float* gbase = sg + n0;
        for (int k = jsub * 4; k < CHUNK; k += 64) {
            float4 pv = *reinterpret_cast<const float4*>(sp + k);
            const float* gw = gbase + k;
            float gv[20];
#pragma unroll
            for (int q = 0; q < 5; q++) {
                float4 t = *reinterpret_cast<const float4*>(gw + 4 * q);
                gv[4 * q + 0] = t.x; gv[4 * q + 1] = t.y;
                gv[4 * q + 2] = t.z; gv[4 * q + 3] = t.w;
            }
            float pj[4] = {pv.x, pv.y, pv.z, pv.w};
#pragma unroll
            for (int dj = 0; dj < 4; dj++)
#pragma unroll
                for (int dn = 0; dn < 16; dn++)
                    acc[dn] = fmaf(pj[dj], gv[dj + dn], acc[dn]);
        }
        __syncthreads();
    }

    // reduce 16-lane j-subgroups via butterfly shuffle (stays in group)
#pragma unroll
    for (int dn = 0; dn < 16; dn++) {
        float v = acc[dn];
        v += __shfl_xor_sync(0xFFFFFFFFu, v, 8);
        v += __shfl_xor_sync(0xFFFFFFFFu, v, 4);
        v += __shfl_xor_sync(0xFFFFFFFFu, v, 2);
        v += __shfl_xor_sync(0xFFFFFFFFu, v, 1);
        acc[dn] = v;
    }
    if (jsub == 0) {
#pragma unroll
        for (int dn = 0; dn < 16; dn++)
            d_Cpart[blockIdx.x][n0 + dn] = acc[dn];
    }

    // block-reduce the 4 scalar sums
    float vals[4] = {s_p, q_p, s_g, q_g};
    for (int v = 0; v < 4; v++) {
        float x = vals[v];
#pragma unroll
        for (int off = 16; off > 0; off >>= 1)
            x += __shfl_down_sync(0xFFFFFFFFu, x, off);
        if ((tid & 31) == 0) red[tid >> 5] = x;
        __syncthreads();
        if (tid == 0) {
            float s = 0.f;
            for (int w = 0; w < NTHREADS / 32; w++) s += red[w];
            d_sums[blockIdx.x][v] = s;
        }
        __syncthreads();
    }

    // ---- last-block election ----
    __threadfence();
    if (tid == 0) {
        unsigned int old = atomicAdd(&d_ticket, 1u);
        s_last = (old == gridDim.x - 1) ? 1 : 0;
    }
    __syncthreads();
    if (!s_last) return;

    // =====================================================================
    // Finalize (runs in the last block; partials are L2-hot)
    // =====================================================================
    const int nblk = gridDim.x;
    __shared__ double sh_sums[4];
    __shared__ double prefp[NL];
    __shared__ double prefq[NL];
    __shared__ double cccsh[NL];

    // ---- cross-block C reduction: one lag per thread, 4 accumulators ----
    double Cn;
    {
        const int lag = tid;
        float a0 = 0.f, a1 = 0.f, a2 = 0.f, a3 = 0.f;
        int b = 0;
        for (; b + 3 < nblk; b += 4) {
            a0 += d_Cpart[b    ][lag];
            a1 += d_Cpart[b + 1][lag];
            a2 += d_Cpart[b + 2][lag];
            a3 += d_Cpart[b + 3][lag];
        }
        for (; b < nblk; b++) a0 += d_Cpart[b][lag];
        Cn = (double)((a0 + a1) + (a2 + a3));
    }

    // ---- scalar sums (4 warps, one value each) ----
    if (tid < 128) {
        int v = tid >> 5, lane = tid & 31;
        double sv = 0.0;
        for (int b = lane; b < nblk; b += 32) sv += (double)d_sums[b][v];
#pragma unroll
        for (int off = 16; off > 0; off >>= 1)
            sv += __shfl_down_sync(0xFFFFFFFFu, sv, off);
        if (lane == 0) sh_sums[v] = sv;
    }

    // ---- tail prefix sums: tail_p(n) = sum_{i=1..n} p[T-i] ----
    {
        double w = (tid >= 1) ? (double)p[T - tid] : 0.0;
        prefp[tid] = w;
        prefq[tid] = w * w;
    }
    __syncthreads();
#pragma unroll
    for (int off = 1; off < NL; off <<= 1) {
        double a = 0.0, b = 0.0;
        if (tid >= off) { a = prefp[tid - off]; b = prefq[tid - off]; }
        __syncthreads();
        prefp[tid] += a; prefq[tid] += b;
        __syncthreads();
    }

    // ---- per-lag CCC ----
    double ccc = 0.0;
    if (tid < NLAGS) {
        double tp = prefp[tid], tq = prefq[tid];   // pref[0] == 0
        const double Td  = (double)T;
        const double rT  = 1.0 / Td;
        const double rT1 = 1.0 / (Td - 1.0);
        double Sp = sh_sums[0] - tp, Qp = sh_sums[1] - tq;
        double Sg = sh_sums[2],      Qg = sh_sums[3];
        double mean_gt   = Sg * rT;
        double var_gt    = (Qg - Sg * Sg * rT) * rT1;
        double mean_pred = Sp * rT;
        double var_pred  = (Qp - Sp * Sp * rT) * rT1;
        double cov       = (Cn - mean_gt * Sp) * rT;
        double dm        = mean_gt - mean_pred;
        double denom     = var_gt + var_pred + dm * dm;
        ccc = 2.0 * cov / denom;
    }
    cccsh[tid] = ccc;   // lags 250..255 contribute 0
    __syncthreads();

#pragma unroll
    for (int off = NL / 2; off > 0; off >>= 1) {
        if (tid < off) cccsh[tid] += cccsh[tid + off];
        __syncthreads();
    }
    if (tid == 0) {
        out[0] = (float)(1.0 - cccsh[0] / (double)NLAGS);
        d_ticket = 0;   // restore for next graph replay
    }
}

extern "C" void kernel_launch(void* const* d_in, const int* in_sizes, int n_in,
                              void* d_out, int out_size) {
    const float* p = (const float*)d_in[0];   // prediction
    const float* g = (const float*)d_in[1];   // ground_truth
    int T = in_sizes[0];
    int nchunks = (T + CHUNK - 1) / CHUNK;
    int grid = nchunks < MAXBLK ? nchunks : MAXBLK;
    fused_kernel<<<grid, NTHREADS>>>(p, g, (float*)d_out, T, nchunks);
}

// round 9
// speedup vs baseline: 1.6283x; 1.5554x over previous
#include <cuda_runtime.h>
#include <cuda_bf16.h>
#include <cstdint>

// CrossCCC via warp-level bf16 MMA (mma.sync.m16n8k16, tensor pipe).
//   j = base + 128k + m  =>  C(n) = sum_st sum_m D_st[m][m+n]
//   A[m][k] = p[base+128k+m]   (128 x 64 bf16)   row-major fragment operand
//   B[u][k] = g[base+128k+u]   (384 x 64 bf16)   col-major fragment operand
//   D = A x B^T in fp32, diagonals n = u - m accumulated into per-warp C rows.
// Scalar stats in fp32 from original data; CCC formula in double in a
// last-block finalizer (atomic ticket). bf16 only touches C' (err ~4e-7).

#define NL        256
#define NLAGS     250
#define KC        64                     // K per supertile
#define SUPER     (128 * KC)             // 8192
#define UW        384                    // N window
#define GWIN      (128 * (KC - 1) + UW)  // 8448
#define NTHREADS  512
#define MAXBLK    256
#define RSTRIDE   72                     // tile row stride in bf16 elems (36 words)

// dynamic smem layout (bytes)
#define OFF_PA    0                       // 128 x 72 bf16 = 18432
#define OFF_GB    18432                   // 384 x 72 bf16 = 55296
#define OFF_CS    (18432 + 55296)         // 64 x 256 f32  = 65536
#define SMEM_BYTES (OFF_CS + 64 * 256 * 4)

__device__ float d_Cpart[MAXBLK][NL];
__device__ float d_sums[MAXBLK][4];
__device__ unsigned int d_ticket;

__device__ __forceinline__ void mma_bf16(float& d0, float& d1, float& d2, float& d3,
                                         uint32_t a0, uint32_t a1, uint32_t a2, uint32_t a3,
                                         uint32_t b0, uint32_t b1) {
    asm volatile(
        "mma.sync.aligned.m16n8k16.row.col.f32.bf16.bf16.f32 "
        "{%0,%1,%2,%3}, {%4,%5,%6,%7}, {%8,%9}, {%0,%1,%2,%3};"
        : "+f"(d0), "+f"(d1), "+f"(d2), "+f"(d3)
        : "r"(a0), "r"(a1), "r"(a2), "r"(a3), "r"(b0), "r"(b1));
}

__global__ void __launch_bounds__(NTHREADS, 1)
ccc_mma_kernel(const float* __restrict__ p, const float* __restrict__ g,
               float* __restrict__ out, int T, int nst) {
    extern __shared__ char smem[];
    __nv_bfloat16* pa = reinterpret_cast<__nv_bfloat16*>(smem + OFF_PA);
    __nv_bfloat16* gb = reinterpret_cast<__nv_bfloat16*>(smem + OFF_GB);
    const uint32_t* pa32 = reinterpret_cast<const uint32_t*>(pa);
    const uint32_t* gb32 = reinterpret_cast<const uint32_t*>(gb);
    float* Cs = reinterpret_cast<float*>(smem + OFF_CS);   // [64][256]

    __shared__ float Cfold[2][NL];
    __shared__ float red[NTHREADS / 32];
    __shared__ int   s_last;

    const int tid  = threadIdx.x;
    const int wid  = tid >> 5, lane = tid & 31;
    const int gid  = lane >> 2, tig = lane & 3;
    const int m0   = (wid & 7) * 16;          // warp's 16 m-rows
    const int nb0  = (wid >> 3) * 24;         // warp's 24 n-tiles

    // zero per-warp C rows
    for (int i = tid; i < 64 * NL; i += NTHREADS) Cs[i] = 0.f;

    float s_p = 0.f, q_p = 0.f, s_g = 0.f, q_g = 0.f;

    for (int st = blockIdx.x; st < nst; st += gridDim.x) {
        const long long base = (long long)st * SUPER;
        const int lim = (int)min((long long)0x7FFFFFFF, (long long)T - base);
        const bool safe = (base + GWIN <= (long long)T);
        __syncthreads();   // Cs/tiles from previous iter fully consumed

        // ---- fill pa[m][k] = p[base+128k+m], stats on p ----
        for (int it = 0; it < SUPER / NTHREADS; it++) {
            int cell = it * NTHREADS + tid;
            int k = cell >> 7, m = cell & 127;
            float v = 0.f;
            if (safe || cell < lim) v = p[base + cell];   // cell == 128k+m
            s_p += v; q_p += v * v;
            pa[m * RSTRIDE + k] = __float2bfloat16(v);
        }
        // ---- fill gb[u][k] = g[base+128k+u], stats on g (u<128 only) ----
        for (int it = 0; it < (KC * UW) / NTHREADS; it++) {
            int cell = it * NTHREADS + tid;
            int k = cell / UW, u = cell - k * UW;
            int j = (k << 7) + u;
            float v = 0.f;
            if (safe || j < lim) v = g[base + j];
            if (u < 128) { s_g += v; q_g += v * v; }
            gb[u * RSTRIDE + k] = __float2bfloat16(v);
        }
        __syncthreads();

        // ---- A fragments for all 4 k-steps (held in registers) ----
        uint32_t af[4][4];
        {
            int r0 = (m0 + gid) * (RSTRIDE / 2) + tig;
            int r1 = r0 + 8 * (RSTRIDE / 2);
#pragma unroll
            for (int ks = 0; ks < 4; ks++) {
                int o = 8 * ks;
                af[ks][0] = pa32[r0 + o];
                af[ks][1] = pa32[r1 + o];
                af[ks][2] = pa32[r0 + o + 4];
                af[ks][3] = pa32[r1 + o + 4];
            }
        }

        // ---- mainloop: 24 n-tiles x 4 k-steps of m16n8k16 ----
        float* Crow = Cs + (wid * 4 + tig) * NL;
        const int rot = 8 * tig;
        for (int nt = 0; nt < 24; nt++) {
            const int u0 = (nb0 + nt) * 8;
            float d0 = 0.f, d1 = 0.f, d2 = 0.f, d3 = 0.f;
            const int brow = (u0 + gid) * (RSTRIDE / 2) + tig;
#pragma unroll
            for (int ks = 0; ks < 4; ks++) {
                uint32_t b0 = gb32[brow + 8 * ks];
                uint32_t b1 = gb32[brow + 8 * ks + 4];
                mma_bf16(d0, d1, d2, d3,
                         af[ks][0], af[ks][1], af[ks][2], af[ks][3], b0, b1);
            }
            // diagonal accumulate: n = u - m
            int n = u0 + 2 * tig - m0 - gid;
            if ((unsigned)n       < NLAGS) Crow[(n     + rot) & 255] += d0;
            if ((unsigned)(n + 1) < NLAGS) Crow[(n + 1 + rot) & 255] += d1;
            if ((unsigned)(n - 8) < NLAGS) Crow[(n - 8 + rot) & 255] += d2;
            if ((unsigned)(n - 7) < NLAGS) Crow[(n - 7 + rot) & 255] += d3;
        }
    }
    __syncthreads();

    // ---- fold 64 rotated C rows -> d_Cpart ----
    {
        int n = tid & 255, grp = tid >> 8;   // grp 0..1
        float v = 0.f;
        for (int a = grp * 32; a < grp * 32 + 32; a++) {
            int t = a & 3;
            v += Cs[a * NL + ((n + 8 * t) & 255)];
        }
        Cfold[grp][n] = v;
    }
    __syncthreads();
    if (tid < NL) d_Cpart[blockIdx.x][tid] = Cfold[0][tid] + Cfold[1][tid];

    // ---- block-reduce scalar sums ----
    float vals[4] = {s_p, q_p, s_g, q_g};
    for (int v = 0; v < 4; v++) {
        float x = vals[v];
#pragma unroll
        for (int off = 16; off > 0; off >>= 1)
            x += __shfl_down_sync(0xFFFFFFFFu, x, off);
        if (lane == 0) red[wid] = x;
        __syncthreads();
        if (tid == 0) {
            float s = 0.f;
            for (int w = 0; w < NTHREADS / 32; w++) s += red[w];
            d_sums[blockIdx.x][v] = s;
        }
        __syncthreads();
    }

    // ---- last-block election ----
    __threadfence();
    if (tid == 0) {
        unsigned int old = atomicAdd(&d_ticket, 1u);
        s_last = (old == gridDim.x - 1) ? 1 : 0;
    }
    __syncthreads();
    if (!s_last) return;

    // ================= finalize (last block) =================
    const int nblk = gridDim.x;
    __shared__ double sh_sums[4];
    __shared__ double prefp[NL];
    __shared__ double prefq[NL];
    __shared__ double cccsh[NL];

    double Cn = 0.0;
    if (tid < NL) {
        const int lag = tid;
        float a0 = 0.f, a1 = 0.f, a2 = 0.f, a3 = 0.f;
        int b = 0;
        for (; b + 3 < nblk; b += 4) {
            a0 += d_Cpart[b    ][lag];
            a1 += d_Cpart[b + 1][lag];
            a2 += d_Cpart[b + 2][lag];
            a3 += d_Cpart[b + 3][lag];
        }
        for (; b < nblk; b++) a0 += d_Cpart[b][lag];
        Cn = (double)((a0 + a1) + (a2 + a3));
    }

    if (tid < 128) {
        int v = tid >> 5, ln = tid & 31;
        double sv = 0.0;
        for (int b = ln; b < nblk; b += 32) sv += (double)d_sums[b][v];
#pragma unroll
        for (int off = 16; off > 0; off >>= 1)
            sv += __shfl_down_sync(0xFFFFFFFFu, sv, off);
        if (ln == 0) sh_sums[v] = sv;
    }

    if (tid < NL) {
        double w = (tid >= 1) ? (double)p[T - tid] : 0.0;
        prefp[tid] = w;
        prefq[tid] = w * w;
    }
    __syncthreads();
#pragma unroll
    for (int off = 1; off < NL; off <<= 1) {
        double a = 0.0, b = 0.0;
        if (tid < NL && tid >= off) { a = prefp[tid - off]; b = prefq[tid - off]; }
        __syncthreads();
        if (tid < NL) { prefp[tid] += a; prefq[tid] += b; }
        __syncthreads();
    }

    double ccc = 0.0;
    if (tid < NLAGS) {
        double tp = prefp[tid], tq = prefq[tid];
        const double Td  = (double)T;
        const double rT  = 1.0 / Td;
        const double rT1 = 1.0 / (Td - 1.0);
        double Sp = sh_sums[0] - tp, Qp = sh_sums[1] - tq;
        double Sg = sh_sums[2],      Qg = sh_sums[3];
        double mean_gt   = Sg * rT;
        double var_gt    = (Qg - Sg * Sg * rT) * rT1;
        double mean_pred = Sp * rT;
        double var_pred  = (Qp - Sp * Sp * rT) * rT1;
        double cov       = (Cn - mean_gt * Sp) * rT;
        double dm        = mean_gt - mean_pred;
        ccc = 2.0 * cov / (var_gt + var_pred + dm * dm);
    }
    if (tid < NL) cccsh[tid] = ccc;
    __syncthreads();
#pragma unroll
    for (int off = NL / 2; off > 0; off >>= 1) {
        if (tid < off) cccsh[tid] += cccsh[tid + off];
        __syncthreads();
    }
    if (tid == 0) {
        out[0] = (float)(1.0 - cccsh[0] / (double)NLAGS);
        d_ticket = 0;
    }
}

extern "C" void kernel_launch(void* const* d_in, const int* in_sizes, int n_in,
                              void* d_out, int out_size) {
    const float* p = (const float*)d_in[0];
    const float* g = (const float*)d_in[1];
    int T = in_sizes[0];
    int nst = (T + SUPER - 1) / SUPER;
    int grid = nst < 148 ? nst : 148;
    if (grid > MAXBLK) grid = MAXBLK;
    cudaFuncSetAttribute(ccc_mma_kernel,
                         cudaFuncAttributeMaxDynamicSharedMemorySize, SMEM_BYTES);
    ccc_mma_kernel<<<grid, NTHREADS, SMEM_BYTES>>>(p, g, (float*)d_out, T, nst);
}